// round 6
// baseline (speedup 1.0000x reference)
#include <cuda_runtime.h>
#include <cuda_bf16.h>
#include <cstdint>

#define GRID  592          // 4 blocks/SM x 148 SMs -> single resident wave
#define TPB   256
#define CHUNK 3000         // int4 elements staged in smem (48000 B)

// Device-global scratch (no allocations allowed). Zero-initialized at load;
// the kernel self-resets counters at the end of every launch.
__device__ unsigned g_partial[GRID];
__device__ unsigned g_arrive;
__device__ unsigned g_done;

// ---------------------------------------------------------------------------
// Robust small-integer scalar decode (int32/int64/float32/float64).
// ---------------------------------------------------------------------------
__device__ __forceinline__ int decode_scalar(const int* p, int dflt) {
    if (p == nullptr) return dflt;
    int w0 = p[0];
    if (w0 >= -1000000 && w0 <= 1000000) {
        if (w0 != 0) return w0;                 // int32 / int64 small value
        int w1 = p[1];
        if (w1 == 0) return 0;
        double d = __hiloint2double(w1, w0);
        if (d >= -1e6 && d <= 1e6) return (int)d;
        return 0;
    }
    float f = __int_as_float(w0);
    if (f >= -1e6f && f <= 1e6f) return (int)f;
    int w1 = p[1];
    double d = __hiloint2double(w1, w0);
    if (d >= -1e6 && d <= 1e6) return (int)d;
    return dflt;
}

// ---------------------------------------------------------------------------
// Pseudo-stochastic shift quantizer (faithful _psto_shift, s >= 1).
// Verified bit-exact vs reference (rel_err = 0.0 in R4/R5).
// ---------------------------------------------------------------------------
__device__ __forceinline__ int uw_psto(int x, int s) {
    int rt   = x >> s;                 // floor(x / 2^s)
    int prob = x & ((1 << s) - 1);     // non-negative floor remainder
    int hs   = s >> 1;
    int qprob = prob >> hs;
    int prn   = (prob & ((1 << hs) - 1)) * (1 + (s & 1));
    int sgn   = (x > 0) - (x < 0);
    int dec   = (qprob <= prn) ? 0 : sgn;
    int gv    = rt + dec;
    return min(127, max(-127, gv));
}

__device__ __forceinline__ unsigned max4abs(int4 v) {
    unsigned a0 = (unsigned)(v.x < 0 ? -v.x : v.x);
    unsigned a1 = (unsigned)(v.y < 0 ? -v.y : v.y);
    unsigned a2 = (unsigned)(v.z < 0 ? -v.z : v.z);
    unsigned a3 = (unsigned)(v.w < 0 ? -v.w : v.w);
    return max(max(a0, a1), max(a2, a3));
}

__device__ __forceinline__ unsigned block_reduce_max(unsigned m, unsigned* s_red) {
    m = __reduce_max_sync(0xffffffffu, m);
    int lane = threadIdx.x & 31;
    int wid  = threadIdx.x >> 5;
    if (lane == 0) s_red[wid] = m;
    __syncthreads();
    unsigned v = 0;
    if (wid == 0) {
        v = (lane < (TPB >> 5)) ? s_red[lane] : 0u;
        v = __reduce_max_sync(0xffffffffu, v);
    }
    return v;  // valid in warp 0
}

// ---------------------------------------------------------------------------
// Fused persistent kernel: one launch does max-reduce + grid barrier + update.
// Each block stages its LAST 48KB grad chunk in smem across the barrier so
// ~27MB of the grad re-read never touches L2/DRAM (LTS is the bottleneck).
// ---------------------------------------------------------------------------
__global__ void __launch_bounds__(TPB, 4) uw_fused_kernel(
    const int4* __restrict__ w4,   // weight promoted to int32 by harness
    const int4* __restrict__ g4,
    const int*  __restrict__ p_err_exp,
    const int*  __restrict__ p_act_in_exp,
    const int*  __restrict__ p_mu,
    float* __restrict__ out_w,
    float* __restrict__ out_g,
    float* __restrict__ out_exp,
    long n4)
{
    __shared__ int4 s_g[CHUNK];
    __shared__ unsigned s_red[32];
    __shared__ unsigned s_bcast;

    const int  tid = threadIdx.x;
    const int  bid = blockIdx.x;

    long per = (n4 + GRID - 1) / GRID;
    long beg = (long)bid * per;
    long end = beg + per; if (end > n4) end = n4; if (end < beg) end = beg;
    long sbeg = end - CHUNK; if (sbeg < beg) sbeg = beg;   // staged region

    // ---------------- Phase A: local max + stage last chunk ----------------
    unsigned m = 0u;
#pragma unroll 4
    for (long i = beg + tid; i < sbeg; i += TPB)
        m = max(m, max4abs(__ldg(&g4[i])));
    for (long i = sbeg + tid; i < end; i += TPB) {
        int4 v = __ldg(&g4[i]);
        s_g[i - sbeg] = v;
        m = max(m, max4abs(v));
    }

    unsigned bm = block_reduce_max(m, s_red);
    if (tid == 0) {
        g_partial[bid] = bm;
        __threadfence();
        atomicAdd(&g_arrive, 1u);
        // Single-wave grid: all blocks resident -> spin is deadlock-free.
        while (atomicAdd(&g_arrive, 0u) < GRID) __nanosleep(64);
        __threadfence();
    }
    __syncthreads();

    // ---------------- Global max (each block scans partials) ----------------
    unsigned gm = 0u;
    for (int i = tid; i < GRID; i += TPB) gm = max(gm, g_partial[i]);
    {
        __syncthreads();  // s_red reuse
        unsigned r = block_reduce_max(gm, s_red);
        if (tid == 0) s_bcast = r;
        __syncthreads();
        gm = s_bcast;
    }

    // ---------------- Scalar branch computation ----------------
    int mu = decode_scalar(p_mu, 7);
    int bw = (gm == 0u) ? 0
             : (int)ceilf(log2f(fmaxf((float)gm, 1.0f)));
    int shift = bw - mu;
    int s = max(shift, 1);
    bool zero_branch  = (bw == 0);
    bool trunc_branch = (shift < 1);

    if (bid == 0 && tid == 0) {
        int gs = (zero_branch || trunc_branch) ? 0 : shift;
        int ee = decode_scalar(p_err_exp, -10);
        int ae = decode_scalar(p_act_in_exp, -7);
        *out_exp = (float)(ee + gs + ae);
    }

    // ---------------- Phase B: elementwise update ----------------
    float4* __restrict__ ow4 = (float4*)out_w;
    float4* __restrict__ og4 = (float4*)out_g;

    // Non-staged portion: grad re-read from global.
#pragma unroll 2
    for (long i = beg + tid; i < sbeg; i += TPB) {
        int4 gv = __ldg(&g4[i]);
        int4 wv = __ldg(&w4[i]);
        int gx[4] = { gv.x, gv.y, gv.z, gv.w };
        int wi[4] = { wv.x, wv.y, wv.z, wv.w };
        float og[4], ow[4];
#pragma unroll
        for (int k = 0; k < 4; k++) {
            int gq;
            if (zero_branch)       gq = 0;
            else if (trunc_branch) gq = (int)(signed char)gx[k];
            else                   gq = uw_psto(gx[k], s);
            int nw = wi[k] - gq;
            nw = min(127, max(-127, nw));
            og[k] = (float)gq;
            ow[k] = (float)nw;
        }
        __stcs(&ow4[i], make_float4(ow[0], ow[1], ow[2], ow[3]));
        __stcs(&og4[i], make_float4(og[0], og[1], og[2], og[3]));
    }
    // Staged portion: grad from shared memory (no LTS read).
    for (long i = sbeg + tid; i < end; i += TPB) {
        int4 gv = s_g[i - sbeg];
        int4 wv = __ldg(&w4[i]);
        int gx[4] = { gv.x, gv.y, gv.z, gv.w };
        int wi[4] = { wv.x, wv.y, wv.z, wv.w };
        float og[4], ow[4];
#pragma unroll
        for (int k = 0; k < 4; k++) {
            int gq;
            if (zero_branch)       gq = 0;
            else if (trunc_branch) gq = (int)(signed char)gx[k];
            else                   gq = uw_psto(gx[k], s);
            int nw = wi[k] - gq;
            nw = min(127, max(-127, nw));
            og[k] = (float)gq;
            ow[k] = (float)nw;
        }
        __stcs(&ow4[i], make_float4(ow[0], ow[1], ow[2], ow[3]));
        __stcs(&og4[i], make_float4(og[0], og[1], og[2], og[3]));
    }

    // ---------------- Self-reset of barrier counters ----------------
    __syncthreads();
    if (tid == 0) {
        unsigned d = atomicAdd(&g_done, 1u);
        if (d == GRID - 1u) {
            // All blocks are past the arrive-spin (they incremented g_done),
            // so resetting is race-free. Next launch sees pristine state.
            atomicExch(&g_arrive, 0u);
            atomicExch(&g_done, 0u);
        }
    }
}

// ---------------------------------------------------------------------------
// Launch. Inputs: weight int32[N] (promoted int8), grad int32[N],
// err_exp, act_in_exp, mu (int32 scalars).
// Output: float32[2N+1] = concat(new_weight, grad, grad_exp).
// ---------------------------------------------------------------------------
extern "C" void kernel_launch(void* const* d_in, const int* in_sizes, int n_in,
                              void* d_out, int out_size)
{
    const int4* w4 = (const int4*)d_in[0];
    const int4* g4 = (const int4*)d_in[1];
    const int* p_err = (n_in > 2) ? (const int*)d_in[2] : nullptr;
    const int* p_act = (n_in > 3) ? (const int*)d_in[3] : nullptr;
    const int* p_mu  = (n_in > 4) ? (const int*)d_in[4] : nullptr;

    long N  = (long)in_sizes[0];
    long n4 = N >> 2;

    float* out   = (float*)d_out;
    float* out_w = out;
    float* out_g = out + N;
    float* out_e = out + 2 * N;

    uw_fused_kernel<<<GRID, TPB>>>(w4, g4, p_err, p_act, p_mu,
                                   out_w, out_g, out_e, n4);
}